// round 6
// baseline (speedup 1.0000x reference)
#include <cuda_runtime.h>
#include <cuda_bf16.h>

#define NPTS 8192
#define DIN  64
#define KNN  16
#define DOUT 128

// Scratch (device globals: no allocation allowed in kernel_launch)
__device__ float g_U[NPTS * DOUT];
__device__ float g_V[NPTS * DOUT];
__device__ float g_sq[NPTS];
__device__ int   g_idx[NPTS * KNN];

// ---------------------------------------------------------------------------
// Kernel A: per-point precompute
//   sq[i]  = |x_i|^2
//   U[i,:] = x_i @ (W1_top - W1_bot) + b1
//   V[i,:] = x_i @ W1_bot
// ---------------------------------------------------------------------------
#define RPB 16
__global__ __launch_bounds__(128) void prep_kernel(const float* __restrict__ x,
                                                   const float* __restrict__ W1,
                                                   const float* __restrict__ b1) {
    __shared__ float xs[RPB][DIN];
    const int t = threadIdx.x;          // 0..127
    const int row0 = blockIdx.x * RPB;

    for (int i = t; i < RPB * DIN; i += 128)
        xs[i >> 6][i & 63] = x[row0 * DIN + i];
    __syncthreads();

    if (t < RPB) {
        float s = 0.f;
        #pragma unroll
        for (int d = 0; d < DIN; d++) { float v = xs[t][d]; s += v * v; }
        g_sq[row0 + t] = s;
    }

    float u[RPB], v[RPB];
    const float bb = b1[t];
    #pragma unroll
    for (int r = 0; r < RPB; r++) { u[r] = bb; v[r] = 0.f; }

    #pragma unroll 4
    for (int d = 0; d < DIN; d++) {
        const float wt = W1[d * DOUT + t];
        const float wb = W1[(d + DIN) * DOUT + t];
        const float wd = wt - wb;
        #pragma unroll
        for (int r = 0; r < RPB; r++) {
            const float xv = xs[r][d];
            u[r] += xv * wd;
            v[r] += xv * wb;
        }
    }
    #pragma unroll
    for (int r = 0; r < RPB; r++) {
        g_U[(row0 + r) * DOUT + t] = u[r];
        g_V[(row0 + r) * DOUT + t] = v[r];
    }
}

// ---------------------------------------------------------------------------
// Kernel B: fused gram + per-row top-16 (the hot kernel)
// 64-row tile per block, sweep 128 column tiles of 64. Ranking key is
// sq[j] - 2*dot(i,j)  (sq[i] is row-constant, does not affect ordering).
// Threshold-filtered candidates go to a shared buffer (cap 64 == tile width,
// overflow impossible), merged into a sorted-16 list by 64 owner threads.
// ---------------------------------------------------------------------------
struct __align__(16) SmemB {
    float As[64][68];       // x row-tile, transposed [d][r]
    float Bs[64][68];       // x col-tile, transposed [d][c]
    float candD[64][65];
    float topD[64][17];
    int   candI[64][65];
    int   topI[64][17];
    float sqB[64];
    float thr[64];
    int   candCnt[64];
};

__global__ __launch_bounds__(256) void topk_kernel(const float* __restrict__ x) {
    extern __shared__ __align__(16) unsigned char smraw[];
    SmemB* sm = reinterpret_cast<SmemB*>(smraw);

    const int tid  = threadIdx.x;
    const int row0 = blockIdx.x * 64;
    const int tx   = tid & 15;   // 16 col groups
    const int ty   = tid >> 4;   // 16 row groups

    // Load A tile (transposed) — coalesced global reads
    for (int i = tid; i < 64 * 64; i += 256) {
        const int r = i >> 6, d = i & 63;
        sm->As[d][r] = x[(row0 + r) * DIN + d];
    }
    // Init top lists
    for (int i = tid; i < 64 * KNN; i += 256) {
        sm->topD[i >> 4][i & 15] = 3.0e38f;
        sm->topI[i >> 4][i & 15] = 0;
    }
    if (tid < 64) { sm->thr[tid] = 3.0e38f; sm->candCnt[tid] = 0; }
    __syncthreads();

    for (int ct = 0; ct < NPTS / 64; ct++) {
        const int c0 = ct * 64;
        // Load B tile (transposed) + norms
        for (int i = tid; i < 64 * 64; i += 256) {
            const int r = i >> 6, d = i & 63;
            sm->Bs[d][r] = x[(c0 + r) * DIN + d];
        }
        if (tid < 64) sm->sqB[tid] = g_sq[c0 + tid];
        __syncthreads();

        // 4x4 micro-tile dot products
        float acc[4][4];
        #pragma unroll
        for (int i = 0; i < 4; i++)
            #pragma unroll
            for (int j = 0; j < 4; j++) acc[i][j] = 0.f;

        #pragma unroll 16
        for (int d = 0; d < DIN; d++) {
            const float4 a = *reinterpret_cast<const float4*>(&sm->As[d][ty * 4]);
            const float4 b = *reinterpret_cast<const float4*>(&sm->Bs[d][tx * 4]);
            acc[0][0] += a.x * b.x; acc[0][1] += a.x * b.y; acc[0][2] += a.x * b.z; acc[0][3] += a.x * b.w;
            acc[1][0] += a.y * b.x; acc[1][1] += a.y * b.y; acc[1][2] += a.y * b.z; acc[1][3] += a.y * b.w;
            acc[2][0] += a.z * b.x; acc[2][1] += a.z * b.y; acc[2][2] += a.z * b.z; acc[2][3] += a.z * b.w;
            acc[3][0] += a.w * b.x; acc[3][1] += a.w * b.y; acc[3][2] += a.w * b.z; acc[3][3] += a.w * b.w;
        }

        // Threshold filter -> candidate append (stale threshold is safe:
        // it only admits extra candidates, never drops true ones)
        #pragma unroll
        for (int i = 0; i < 4; i++) {
            const int r = ty * 4 + i;
            const float th = sm->thr[r];
            #pragma unroll
            for (int j = 0; j < 4; j++) {
                const int c = tx * 4 + j;
                const float key = fmaf(-2.0f, acc[i][j], sm->sqB[c]);
                if (key < th) {
                    const int p = atomicAdd(&sm->candCnt[r], 1);
                    sm->candD[r][p] = key;
                    sm->candI[r][p] = c0 + c;
                }
            }
        }
        __syncthreads();

        // Merge candidates into sorted top-16 (one owner thread per row)
        if (tid < 64) {
            const int r = tid;
            const int n = sm->candCnt[r];
            float worst = sm->topD[r][KNN - 1];
            for (int c = 0; c < n; c++) {
                const float kd = sm->candD[r][c];
                if (kd < worst) {
                    const int ci = sm->candI[r][c];
                    int p = KNN - 1;
                    while (p > 0 && sm->topD[r][p - 1] > kd) {
                        sm->topD[r][p] = sm->topD[r][p - 1];
                        sm->topI[r][p] = sm->topI[r][p - 1];
                        p--;
                    }
                    sm->topD[r][p] = kd;
                    sm->topI[r][p] = ci;
                    worst = sm->topD[r][KNN - 1];
                }
            }
            sm->thr[r] = worst;
            sm->candCnt[r] = 0;
        }
        __syncthreads();
    }

    // Emit neighbor indices
    for (int i = tid; i < 64 * KNN; i += 256)
        g_idx[(row0 + (i >> 4)) * KNN + (i & 15)] = sm->topI[i >> 4][i & 15];
}

// ---------------------------------------------------------------------------
// Kernel C: gather + relu + mean over k, then @W2 + b2
//   acc[i,:] = mean_j relu(U[i,:] + V[idx[i,j],:])
//   out[i,:] = acc[i,:] @ W2 + b2
// ---------------------------------------------------------------------------
__global__ __launch_bounds__(128) void out_kernel(const float* __restrict__ W2,
                                                  const float* __restrict__ b2,
                                                  float* __restrict__ out) {
    __shared__ float accS[16][DOUT];
    const int t = threadIdx.x;            // 0..127 == feature index
    const int row0 = blockIdx.x * 16;

    for (int r = 0; r < 16; r++) {
        const int row = row0 + r;
        const float u = g_U[row * DOUT + t];
        float a = 0.f;
        #pragma unroll
        for (int j = 0; j < KNN; j++) {
            const int nb = g_idx[row * KNN + j];
            a += fmaxf(u + g_V[nb * DOUT + t], 0.f);
        }
        accS[r][t] = a * (1.0f / KNN);
    }
    __syncthreads();

    const float bb = b2[t];
    for (int r = 0; r < 16; r++) {
        float o = bb;
        #pragma unroll 16
        for (int m = 0; m < DOUT; m++)
            o += accS[r][m] * W2[m * DOUT + t];   // coalesced, L1-resident
        out[(row0 + r) * DOUT + t] = o;
    }
}

// ---------------------------------------------------------------------------
extern "C" void kernel_launch(void* const* d_in, const int* in_sizes, int n_in,
                              void* d_out, int out_size) {
    (void)in_sizes; (void)n_in; (void)out_size;
    const float* x  = (const float*)d_in[0];
    const float* W1 = (const float*)d_in[1];
    const float* b1 = (const float*)d_in[2];
    const float* W2 = (const float*)d_in[3];
    const float* b2 = (const float*)d_in[4];
    float* out = (float*)d_out;

    cudaFuncSetAttribute(topk_kernel, cudaFuncAttributeMaxDynamicSharedMemorySize,
                         (int)sizeof(SmemB));

    prep_kernel<<<NPTS / RPB, 128>>>(x, W1, b1);
    topk_kernel<<<NPTS / 64, 256, sizeof(SmemB)>>>(x);
    out_kernel<<<NPTS / 16, 128>>>(W2, b2, out);
}

// round 7
// speedup vs baseline: 1.1622x; 1.1622x over previous
#include <cuda_runtime.h>
#include <cuda_bf16.h>

#define NPTS 8192
#define DIN  64
#define KNN  16
#define DOUT 128

// Scratch (device globals: no allocation allowed in kernel_launch)
__device__ float g_U[NPTS * DOUT];
__device__ float g_V[NPTS * DOUT];
__device__ float g_sq[NPTS];
__device__ int   g_idx[NPTS * KNN];

// Packed fp32x2 FMA: d = a*b + c per 32-bit lane (FFMA2 in SASS).
#define FMA_F32X2(d_, a_, b_, c_) \
    asm("fma.rn.f32x2 %0, %1, %2, %3;" : "=l"(d_) : "l"(a_), "l"(b_), "l"(c_))

// ---------------------------------------------------------------------------
// Kernel A: per-point precompute
//   sq[i]  = |x_i|^2
//   U[i,:] = x_i @ (W1_top - W1_bot) + b1
//   V[i,:] = x_i @ W1_bot
// ---------------------------------------------------------------------------
#define RPB 16
__global__ __launch_bounds__(128) void prep_kernel(const float* __restrict__ x,
                                                   const float* __restrict__ W1,
                                                   const float* __restrict__ b1) {
    __shared__ float xs[RPB][DIN];
    const int t = threadIdx.x;          // 0..127
    const int row0 = blockIdx.x * RPB;

    for (int i = t; i < RPB * DIN; i += 128)
        xs[i >> 6][i & 63] = x[row0 * DIN + i];
    __syncthreads();

    if (t < RPB) {
        float s = 0.f;
        #pragma unroll
        for (int d = 0; d < DIN; d++) { float v = xs[t][d]; s += v * v; }
        g_sq[row0 + t] = s;
    }

    float u[RPB], v[RPB];
    const float bb = b1[t];
    #pragma unroll
    for (int r = 0; r < RPB; r++) { u[r] = bb; v[r] = 0.f; }

    #pragma unroll 4
    for (int d = 0; d < DIN; d++) {
        const float wt = W1[d * DOUT + t];
        const float wb = W1[(d + DIN) * DOUT + t];
        const float wd = wt - wb;
        #pragma unroll
        for (int r = 0; r < RPB; r++) {
            const float xv = xs[r][d];
            u[r] += xv * wd;
            v[r] += xv * wb;
        }
    }
    #pragma unroll
    for (int r = 0; r < RPB; r++) {
        g_U[(row0 + r) * DOUT + t] = u[r];
        g_V[(row0 + r) * DOUT + t] = v[r];
    }
}

// ---------------------------------------------------------------------------
// Kernel B: fused gram + per-row top-16 via packed FFMA2.
//   tile: 64 rows x 128 cols per ct iteration (64 iterations).
//   A tile stored DUPLICATED per row in smem -> row-broadcast pairs load
//   directly as b64, no packing movs. B tile stored with a (block+2d)&31
//   swizzle: store and compute-load both bank-conflict-free.
//   Key = sq[j] - 2*dot(i,j); threshold filter -> candidates -> serial merge.
// ---------------------------------------------------------------------------
#define CTILE 128
#define RTILE 64
#define NCT   (NPTS / CTILE)

struct __align__(16) SmemZ {
    float As2[64 * 132];      // dup A tile: As2[d*132 + 2r(+1)] = a[r]
    float Bs [64 * 132];      // swizzled B tile
    float candD[RTILE][130];
    int   candI[RTILE][130];
    float topD[RTILE][17];
    int   topI[RTILE][17];
    float sqB[CTILE];
    float thr[RTILE];
    int   candCnt[RTILE];
};

__global__ __launch_bounds__(256) void topk_kernel(const float* __restrict__ x) {
    extern __shared__ __align__(16) unsigned char smraw[];
    SmemZ* sm = reinterpret_cast<SmemZ*>(smraw);

    const int tid  = threadIdx.x;
    const int row0 = blockIdx.x * RTILE;
    const int tx   = tid & 15;            // 16 col groups x 8 cols
    const int ty   = tid >> 4;            // 16 row groups x 4 rows
    const int w    = tid >> 5;            // warp id (B-staging)
    const int l    = tid & 31;
    const int cbase = w * 16 + (l & 3);   // B-staging point base (+4m)
    const int dbase = l >> 2;             // B-staging dim base (+8k)

    // ---- A tile (duplicated), one-time ----
    for (int i = tid; i < RTILE * DIN; i += 256) {
        const int d = i & 63, r = i >> 6;
        const float v = x[(row0 + r) * DIN + d];
        sm->As2[d * 132 + 2 * r]     = v;
        sm->As2[d * 132 + 2 * r + 1] = v;
    }
    for (int i = tid; i < RTILE * KNN; i += 256) {
        sm->topD[i >> 4][i & 15] = 3.0e38f;
        sm->topI[i >> 4][i & 15] = 0;
    }
    if (tid < RTILE) { sm->thr[tid] = 3.0e38f; sm->candCnt[tid] = 0; }

    // ---- prefetch B tile 0 into registers ----
    float pf[32];
    #pragma unroll
    for (int m = 0; m < 4; m++)
        #pragma unroll
        for (int k = 0; k < 8; k++)
            pf[m * 8 + k] = x[(cbase + 4 * m) * DIN + (dbase + 8 * k)];
    __syncthreads();

    const unsigned long long NEG2 = 0xC0000000C0000000ULL;  // (-2.f, -2.f)

    for (int ct = 0; ct < NCT; ct++) {
        const int c0 = ct * CTILE;

        // ---- stage: regs -> swizzled Bs, plus sqB ----
        if (tid < CTILE) sm->sqB[tid] = g_sq[c0 + tid];
        #pragma unroll
        for (int m = 0; m < 4; m++) {
            const int blk = w * 4 + m;                  // c_local>>2
            const int c3  = l & 3;
            #pragma unroll
            for (int k = 0; k < 8; k++) {
                const int dd = dbase + 8 * k;
                sm->Bs[dd * 132 + (((blk + 2 * dd) & 31) << 2) + c3] = pf[m * 8 + k];
            }
        }
        __syncthreads();   // (1) Bs/sqB ready; prev merge complete

        // ---- prefetch next tile (latency hidden behind compute) ----
        {
            const int c0n = (ct + 1 < NCT) ? (ct + 1) * CTILE : 0;
            #pragma unroll
            for (int m = 0; m < 4; m++)
                #pragma unroll
                for (int k = 0; k < 8; k++)
                    pf[m * 8 + k] = x[(c0n + cbase + 4 * m) * DIN + (dbase + 8 * k)];
        }

        // ---- 4x8 micro-tile dot products, packed f32x2 ----
        unsigned long long acc[4][4];
        #pragma unroll
        for (int i = 0; i < 4; i++)
            #pragma unroll
            for (int p = 0; p < 4; p++) acc[i][p] = 0ULL;

        #pragma unroll 8
        for (int d = 0; d < DIN; d++) {
            const float* arow = &sm->As2[d * 132 + ty * 8];
            const ulonglong2 aA = *reinterpret_cast<const ulonglong2*>(arow);      // (a0,a0),(a1,a1)
            const ulonglong2 aB = *reinterpret_cast<const ulonglong2*>(arow + 4);  // (a2,a2),(a3,a3)
            const float* brow = &sm->Bs[d * 132];
            const ulonglong2 b0 = *reinterpret_cast<const ulonglong2*>(
                brow + (((2 * tx     + 2 * d) & 31) << 2));
            const ulonglong2 b1 = *reinterpret_cast<const ulonglong2*>(
                brow + (((2 * tx + 1 + 2 * d) & 31) << 2));
            FMA_F32X2(acc[0][0], aA.x, b0.x, acc[0][0]);
            FMA_F32X2(acc[0][1], aA.x, b0.y, acc[0][1]);
            FMA_F32X2(acc[0][2], aA.x, b1.x, acc[0][2]);
            FMA_F32X2(acc[0][3], aA.x, b1.y, acc[0][3]);
            FMA_F32X2(acc[1][0], aA.y, b0.x, acc[1][0]);
            FMA_F32X2(acc[1][1], aA.y, b0.y, acc[1][1]);
            FMA_F32X2(acc[1][2], aA.y, b1.x, acc[1][2]);
            FMA_F32X2(acc[1][3], aA.y, b1.y, acc[1][3]);
            FMA_F32X2(acc[2][0], aB.x, b0.x, acc[2][0]);
            FMA_F32X2(acc[2][1], aB.x, b0.y, acc[2][1]);
            FMA_F32X2(acc[2][2], aB.x, b1.x, acc[2][2]);
            FMA_F32X2(acc[2][3], aB.x, b1.y, acc[2][3]);
            FMA_F32X2(acc[3][0], aB.y, b0.x, acc[3][0]);
            FMA_F32X2(acc[3][1], aB.y, b0.y, acc[3][1]);
            FMA_F32X2(acc[3][2], aB.y, b1.x, acc[3][2]);
            FMA_F32X2(acc[3][3], aB.y, b1.y, acc[3][3]);
        }

        // ---- threshold filter -> candidate append (stale thr is safe) ----
        #pragma unroll
        for (int i = 0; i < 4; i++) {
            const int r = ty * 4 + i;
            const float th = sm->thr[r];
            #pragma unroll
            for (int p = 0; p < 4; p++) {
                const unsigned long long sq2 =
                    *reinterpret_cast<const unsigned long long*>(&sm->sqB[tx * 8 + 2 * p]);
                unsigned long long kp;
                FMA_F32X2(kp, acc[i][p], NEG2, sq2);   // sq - 2*dot
                const float k0 = __uint_as_float((unsigned int)kp);
                const float k1 = __uint_as_float((unsigned int)(kp >> 32));
                if (k0 < th) {
                    const int q = atomicAdd(&sm->candCnt[r], 1);
                    sm->candD[r][q] = k0;
                    sm->candI[r][q] = c0 + tx * 8 + 2 * p;
                }
                if (k1 < th) {
                    const int q = atomicAdd(&sm->candCnt[r], 1);
                    sm->candD[r][q] = k1;
                    sm->candI[r][q] = c0 + tx * 8 + 2 * p + 1;
                }
            }
        }
        __syncthreads();   // (2) candidates complete

        // ---- merge (owner thread per row); next iter's sync(1) covers it ----
        if (tid < RTILE) {
            const int r = tid;
            const int n = sm->candCnt[r];
            if (n > 0) {
                float worst = sm->topD[r][KNN - 1];
                for (int c = 0; c < n; c++) {
                    const float kd = sm->candD[r][c];
                    if (kd < worst) {
                        const int ci = sm->candI[r][c];
                        int p = KNN - 1;
                        while (p > 0 && sm->topD[r][p - 1] > kd) {
                            sm->topD[r][p] = sm->topD[r][p - 1];
                            sm->topI[r][p] = sm->topI[r][p - 1];
                            p--;
                        }
                        sm->topD[r][p] = kd;
                        sm->topI[r][p] = ci;
                        worst = sm->topD[r][KNN - 1];
                    }
                }
                sm->thr[r] = worst;
                sm->candCnt[r] = 0;
            }
        }
    }
    __syncthreads();

    // Emit neighbor indices
    for (int i = tid; i < RTILE * KNN; i += 256)
        g_idx[(row0 + (i >> 4)) * KNN + (i & 15)] = sm->topI[i >> 4][i & 15];
}

// ---------------------------------------------------------------------------
// Kernel C: gather + relu + mean over k, then @W2 + b2
//   acc[i,:] = mean_j relu(U[i,:] + V[idx[i,j],:])
//   out[i,:] = acc[i,:] @ W2 + b2
// ---------------------------------------------------------------------------
__global__ __launch_bounds__(128) void out_kernel(const float* __restrict__ W2,
                                                  const float* __restrict__ b2,
                                                  float* __restrict__ out) {
    __shared__ float accS[16][DOUT];
    const int t = threadIdx.x;            // 0..127 == feature index
    const int row0 = blockIdx.x * 16;

    for (int r = 0; r < 16; r++) {
        const int row = row0 + r;
        const float u = g_U[row * DOUT + t];
        float a = 0.f;
        #pragma unroll
        for (int j = 0; j < KNN; j++) {
            const int nb = g_idx[row * KNN + j];
            a += fmaxf(u + g_V[nb * DOUT + t], 0.f);
        }
        accS[r][t] = a * (1.0f / KNN);
    }
    __syncthreads();

    const float bb = b2[t];
    for (int r = 0; r < 16; r++) {
        float o = bb;
        #pragma unroll 16
        for (int m = 0; m < DOUT; m++)
            o += accS[r][m] * W2[m * DOUT + t];   // coalesced, L1-resident
        out[(row0 + r) * DOUT + t] = o;
    }
}

// ---------------------------------------------------------------------------
extern "C" void kernel_launch(void* const* d_in, const int* in_sizes, int n_in,
                              void* d_out, int out_size) {
    (void)in_sizes; (void)n_in; (void)out_size;
    const float* x  = (const float*)d_in[0];
    const float* W1 = (const float*)d_in[1];
    const float* b1 = (const float*)d_in[2];
    const float* W2 = (const float*)d_in[3];
    const float* b2 = (const float*)d_in[4];
    float* out = (float*)d_out;

    cudaFuncSetAttribute(topk_kernel, cudaFuncAttributeMaxDynamicSharedMemorySize,
                         (int)sizeof(SmemZ));

    prep_kernel<<<NPTS / RPB, 128>>>(x, W1, b1);
    topk_kernel<<<NPTS / RTILE, 256, sizeof(SmemZ)>>>(x);
    out_kernel<<<NPTS / 16, 128>>>(W2, b2, out);
}